// round 16
// baseline (speedup 1.0000x reference)
#include <cuda_runtime.h>
#include <math.h>

#define Bb 2
#define Cc 64
#define Hh 384
#define Ww 384
#define HW (Hh*Ww)            // 147456
#define NTOT (Bb*Cc*HW)       // 18874368
#define HH 48
#define WW 48
#define LLEN HW               // 147456
#define NPATCH (Bb*Cc*HH*WW)  // 294912

typedef unsigned long long ull;

// ------------------- scratch (device globals) -----------------------------
__device__ float g_bA[NTOT];      // hidden -> o_spatial
__device__ float g_bB[2*NTOT];    // nir_hidden (128 ch/batch)
__device__ float g_bC[NTOT];      // q
__device__ float g_bE[NTOT];      // qf -> conv_mid out
__device__ float g_bF[NTOT];      // kf
__device__ float g_bG[NTOT];      // pooled output

__device__ float g_DCTM[64];      // [a*8+m]
__device__ float g_IDCTM[64];     // [m*8+a]
__device__ float g_sqq[128];
__device__ float g_sqk[128];
__device__ float g_S[8*256];
__device__ float g_attn[8*256];
__device__ float g_lam;

// ------------------- packed f32x2 helpers (sm_100+) -----------------------
__device__ __forceinline__ ull pk2(float lo, float hi) {
    ull r; asm("mov.b64 %0, {%1,%2};" : "=l"(r) : "f"(lo), "f"(hi)); return r;
}
#define FMA2(d, a, b, c) asm("fma.rn.f32x2 %0, %1, %2, %3;" : "=l"(d) : "l"(a), "l"(b), "l"(c))

// ------------------- init ---------------------------------------------------
__global__ void k_init(const float* __restrict__ lq1, const float* __restrict__ lk1,
                       const float* __restrict__ lq2, const float* __restrict__ lk2)
{
    int t = threadIdx.x;  // 64 threads
    if (t < 64) {
        int a = t >> 3, m = t & 7;
        double cv = 2.0 * cos(3.14159265358979323846 * (double)((2*m+1)*a) / 16.0);
        g_DCTM[a*8+m] = (float)cv;
        g_IDCTM[m*8+a] = (float)(cv / (a == 0 ? 32.0 : 16.0));
    }
    if (t < 32) {
        float s1 = lq1[t]*lk1[t] + lq1[t+32]*lk1[t+32];
        float s2 = lq2[t]*lk2[t] + lq2[t+32]*lk2[t+32];
        #pragma unroll
        for (int off = 16; off; off >>= 1) {
            s1 += __shfl_xor_sync(0xffffffffu, s1, off);
            s2 += __shfl_xor_sync(0xffffffffu, s2, off);
        }
        if (t == 0) {
            float lam_init = 0.8f - 0.6f * (float)exp(-1.8);
            g_lam = expf(s1) - expf(s2) + lam_init;
        }
    }
    for (int i = t; i < 2048; i += 64) g_S[i] = 0.f;
    for (int i = t; i < 128;  i += 64) { g_sqq[i] = 0.f; g_sqk[i] = 0.f; }
}

// ------------------- conv1x1 (R15 variant — 59.1us, near FFMA2 floor) -----
#define WKS 68
__global__ void __launch_bounds__(128, 4) k_conv1x1(
    const float* __restrict__ in, const float* __restrict__ w,
    float* __restrict__ out, int OCtot, int ocOff)
{
    extern __shared__ char smraw[];
    float* wsf = (float*)smraw;                      // [64 k][68 oc]  17.4KB
    float* xs  = (float*)(smraw + 64*WKS*4);         // [64 ic][128 px] 32KB
    int ocBase = blockIdx.z * 64 + ocOff;
    int b = blockIdx.y;
    int tid = threadIdx.x;

    #pragma unroll
    for (int r = 0; r < 32; r++) {
        int t = r*128 + tid;           // t = oc*64 + k
        int oc = t >> 6, k = t & 63;
        wsf[k*WKS + oc] = __ldg(w + ocBase*64 + t);
    }
    const float* inb = in + (size_t)b*64*HW + blockIdx.x*128;
    #pragma unroll
    for (int r = 0; r < 16; r++) {
        int idx = r*128 + tid;
        int ic  = idx >> 5;
        int c4  = (idx & 31) * 4;
        *(float4*)(xs + ic*128 + c4) = *(const float4*)(inb + (size_t)ic*HW + c4);
    }
    __syncthreads();

    int ocg = tid >> 4;
    int pxg = tid & 15;
    int oc0 = ocg * 8;
    int px0 = pxg * 4;

    ull acc[8][4];
    #pragma unroll
    for (int j = 0; j < 8; j++)
        #pragma unroll
        for (int t = 0; t < 4; t++) acc[j][t] = 0ULL;

    #pragma unroll 4
    for (int k = 0; k < 64; k++) {
        const float* wr = wsf + k*WKS + oc0;
        float4 w0 = *(const float4*)(wr);
        float4 w1 = *(const float4*)(wr + 4);
        const float* xr = xs + k*128 + px0;
        ulonglong2 p0 = *(const ulonglong2*)(xr);
        ulonglong2 p1 = *(const ulonglong2*)(xr + 64);
        float wf[8] = {w0.x, w0.y, w0.z, w0.w, w1.x, w1.y, w1.z, w1.w};
        #pragma unroll
        for (int j = 0; j < 8; j++) {
            ull wv = pk2(wf[j], wf[j]);
            FMA2(acc[j][0], wv, p0.x, acc[j][0]);
            FMA2(acc[j][1], wv, p0.y, acc[j][1]);
            FMA2(acc[j][2], wv, p1.x, acc[j][2]);
            FMA2(acc[j][3], wv, p1.y, acc[j][3]);
        }
    }

    float* outb = out + ((size_t)b*OCtot + ocBase + oc0)*HW + blockIdx.x*128 + px0;
    #pragma unroll
    for (int j = 0; j < 8; j++) {
        ulonglong2 v0; v0.x = acc[j][0]; v0.y = acc[j][1];
        ulonglong2 v1; v1.x = acc[j][2]; v1.y = acc[j][3];
        *(ulonglong2*)(outb + (size_t)j*HW)      = v0;
        *(ulonglong2*)(outb + (size_t)j*HW + 64) = v1;
    }
}
#define CONV_SMEM (64*WKS*4 + 32768)

// ------------------- row loader: 6 values around aligned 4-px group -------
__device__ __forceinline__ void load6(const float* __restrict__ row, int x, float v[6])
{
    float4 c = *(const float4*)(row + x);
    v[1] = c.x; v[2] = c.y; v[3] = c.z; v[4] = c.w;
    v[0] = (x > 0)      ? row[x-1] : 0.f;
    v[5] = (x+4 < Ww)   ? row[x+4] : 0.f;
}

// ------------------- depthwise 3x3, 8 px/thread (q path) ------------------
__global__ void __launch_bounds__(256) k_dw3v2(
    const float* __restrict__ in, const float* __restrict__ w9,
    float* __restrict__ out, int inChPerB, int chOff)
{
    int g = blockIdx.x*256 + threadIdx.x;
    int x  = (g % 96) * 4;
    int y  = ((g / 96) % 192) * 2;
    int bc = g / 18432;                 // 96*192
    int b = bc >> 6, ch = bc & 63;
    int wch = chOff + ch;
    const float* ip = in + ((size_t)b*inChPerB + wch)*HW;
    float w[9];
    #pragma unroll
    for (int i = 0; i < 9; i++) w[i] = __ldg(w9 + wch*9 + i);

    float vr[4][6];
    #pragma unroll
    for (int r = 0; r < 4; r++) {
        int yy = y - 1 + r;
        if ((unsigned)yy < (unsigned)Hh) load6(ip + yy*Ww, x, vr[r]);
        else { vr[r][0]=0.f; vr[r][1]=0.f; vr[r][2]=0.f; vr[r][3]=0.f; vr[r][4]=0.f; vr[r][5]=0.f; }
    }
    float a0[4] = {0,0,0,0}, a1[4] = {0,0,0,0};
    #pragma unroll
    for (int dy = 0; dy < 3; dy++) {
        const float* wr = w + dy*3;
        #pragma unroll
        for (int j = 0; j < 4; j++) {
            a0[j] += wr[0]*vr[dy][j]   + wr[1]*vr[dy][j+1]   + wr[2]*vr[dy][j+2];
            a1[j] += wr[0]*vr[dy+1][j] + wr[1]*vr[dy+1][j+1] + wr[2]*vr[dy+1][j+2];
        }
    }
    float* op = out + (size_t)bc*HW + y*Ww + x;
    *(float4*)(op)      = make_float4(a0[0], a0[1], a0[2], a0[3]);
    *(float4*)(op + Ww) = make_float4(a1[0], a1[1], a1[2], a1[3]);
}

// ------------------- load 10 halo floats (cols x0-1..x0+8) of one row -----
__device__ __forceinline__ void loadrow10(const float* __restrict__ ip,
                                          int y, int x0, float f[10])
{
    if ((unsigned)y >= (unsigned)Hh) {
        #pragma unroll
        for (int i = 0; i < 10; i++) f[i] = 0.f;
        return;
    }
    const float* row = ip + y*Ww;
    float4 b0 = *(const float4*)(row + x0);
    float4 b1 = *(const float4*)(row + x0 + 4);
    f[1]=b0.x; f[2]=b0.y; f[3]=b0.z; f[4]=b0.w;
    f[5]=b1.x; f[6]=b1.y; f[7]=b1.z; f[8]=b1.w;
    f[0] = (x0 > 0)      ? row[x0-1] : 0.f;
    f[9] = (x0+8 < Ww)   ? row[x0+8] : 0.f;
}

// ------------------- fused: q-DCT + inline-dw3(k)-DCT + sumsq -------------
__global__ void __launch_bounds__(128) k_dct2(
    const float* __restrict__ q, const float* __restrict__ nh,
    const float* __restrict__ wdwn,
    float* __restrict__ qf, float* __restrict__ kf)
{
    __shared__ float M[64];
    __shared__ float redq[4], redk[4];
    int tid = threadIdx.x;
    if (tid < 64) M[tid] = g_DCTM[tid];
    __syncthreads();
    int p = blockIdx.x*128 + tid;
    int pw = p % WW;
    int t2 = p / WW;
    int ph = t2 % HH;
    int bc = t2 / HH;
    int b = bc >> 6, ch = bc & 63;

    // ---- q DCT ----
    const float* ipq = q + (size_t)bc*HW + ph*8*Ww + pw*8;
    float tmp[8][8];
    #pragma unroll
    for (int m = 0; m < 8; m++) {
        float4 v0 = *(const float4*)(ipq + m*Ww);
        float4 v1 = *(const float4*)(ipq + m*Ww + 4);
        float r[8] = {v0.x, v0.y, v0.z, v0.w, v1.x, v1.y, v1.z, v1.w};
        #pragma unroll
        for (int bb = 0; bb < 8; bb++) {
            float s = 0.f;
            #pragma unroll
            for (int n = 0; n < 8; n++) s += r[n] * M[bb*8+n];
            tmp[m][bb] = s;
        }
    }
    float* qp = qf + (size_t)p*64;
    float ssq = 0.f;
    #pragma unroll
    for (int a = 0; a < 8; a++) {
        float y[8];
        #pragma unroll
        for (int bb = 0; bb < 8; bb++) {
            float s = 0.f;
            #pragma unroll
            for (int m = 0; m < 8; m++) s += M[a*8+m] * tmp[m][bb];
            y[bb] = s;
            ssq += s*s;
        }
        *(float4*)(qp + a*8)     = make_float4(y[0], y[1], y[2], y[3]);
        *(float4*)(qp + a*8 + 4) = make_float4(y[4], y[5], y[6], y[7]);
    }

    // ---- k = dw3(nir_hidden[ch]) computed inline, then DCT ----
    const float* ipk = nh + ((size_t)b*128 + ch)*HW;
    float wk[9];
    #pragma unroll
    for (int i = 0; i < 9; i++) wk[i] = __ldg(wdwn + ch*9 + i);
    int y0 = ph*8, x0 = pw*8;

    float rA[10], rB[10], rC[10];
    loadrow10(ipk, y0-1, x0, rA);
    loadrow10(ipk, y0,   x0, rB);
    #pragma unroll
    for (int m = 0; m < 8; m++) {
        loadrow10(ipk, y0+m+1, x0, rC);
        float r[8];
        #pragma unroll
        for (int j = 0; j < 8; j++) {
            r[j] = wk[0]*rA[j] + wk[1]*rA[j+1] + wk[2]*rA[j+2]
                 + wk[3]*rB[j] + wk[4]*rB[j+1] + wk[5]*rB[j+2]
                 + wk[6]*rC[j] + wk[7]*rC[j+1] + wk[8]*rC[j+2];
        }
        #pragma unroll
        for (int bb = 0; bb < 8; bb++) {
            float s = 0.f;
            #pragma unroll
            for (int n = 0; n < 8; n++) s += r[n] * M[bb*8+n];
            tmp[m][bb] = s;
        }
        #pragma unroll
        for (int i = 0; i < 10; i++) { rA[i] = rB[i]; rB[i] = rC[i]; }
    }
    float* kp = kf + (size_t)p*64;
    float ssk = 0.f;
    #pragma unroll
    for (int a = 0; a < 8; a++) {
        float y[8];
        #pragma unroll
        for (int bb = 0; bb < 8; bb++) {
            float s = 0.f;
            #pragma unroll
            for (int m = 0; m < 8; m++) s += M[a*8+m] * tmp[m][bb];
            y[bb] = s;
            ssk += s*s;
        }
        *(float4*)(kp + a*8)     = make_float4(y[0], y[1], y[2], y[3]);
        *(float4*)(kp + a*8 + 4) = make_float4(y[4], y[5], y[6], y[7]);
    }

    #pragma unroll
    for (int off = 16; off; off >>= 1) {
        ssq += __shfl_xor_sync(0xffffffffu, ssq, off);
        ssk += __shfl_xor_sync(0xffffffffu, ssk, off);
    }
    int lane = tid & 31, wd = tid >> 5;
    if (lane == 0) { redq[wd] = ssq; redk[wd] = ssk; }
    __syncthreads();
    if (tid == 0) {
        atomicAdd(&g_sqq[bc], redq[0]+redq[1]+redq[2]+redq[3]);
        atomicAdd(&g_sqk[bc], redk[0]+redk[1]+redk[2]+redk[3]);
    }
}

// ------------------- Gram matrices S[bh][c][d] = <qf_c, kf_d> -------------
__global__ void k_dot(const float* __restrict__ qf, const float* __restrict__ kf)
{
    int bh = blockIdx.y; int b = bh >> 2, h = bh & 3;
    const float* qb = qf + ((size_t)b*64 + h*16)*LLEN;
    const float* kb = kf + ((size_t)b*64 + h*16)*LLEN;
    int tid = threadIdx.x;
    int c = tid >> 4, d = tid & 15;
    __shared__ float qs[16][65], ks[16][65];
    float acc = 0.f;
    int l0 = blockIdx.x * 4096;
    for (int lt = 0; lt < 4096; lt += 64) {
        int base = l0 + lt;
        for (int t = tid; t < 1024; t += 256) {
            int r = t >> 6, i = t & 63;
            qs[r][i] = qb[(size_t)r*LLEN + base + i];
            ks[r][i] = kb[(size_t)r*LLEN + base + i];
        }
        __syncthreads();
        #pragma unroll
        for (int i = 0; i < 64; i++) acc += qs[c][i] * ks[d][i];
        __syncthreads();
    }
    atomicAdd(&g_S[bh*256 + tid], acc);
}

// ------------------- finalize logits + softmax over d ---------------------
__global__ void k_softmax(const float* __restrict__ temp)
{
    int bh = blockIdx.x; int b = bh >> 2, h = bh & 3;
    int tid = threadIdx.x; int c = tid >> 4, d = tid & 15;
    float nq = fmaxf(sqrtf(g_sqq[b*64 + h*16 + c]), 1e-12f);
    float nk = fmaxf(sqrtf(g_sqk[b*64 + h*16 + d]), 1e-12f);
    float logit = g_S[bh*256 + tid] / (nq*nk) * temp[h];
    float mx = logit;
    #pragma unroll
    for (int off = 8; off; off >>= 1)
        mx = fmaxf(mx, __shfl_xor_sync(0xffffffffu, mx, off, 16));
    float e = expf(logit - mx);
    float s = e;
    #pragma unroll
    for (int off = 8; off; off >>= 1)
        s += __shfl_xor_sync(0xffffffffu, s, off, 16);
    g_attn[bh*256 + tid] = e / s;
}

// ------------------- fused attn-apply + IDCT (out1 = qf*kf on the fly) ----
#define SMP 1028   // padded stride per patch (floats)
__global__ void __launch_bounds__(128) k_applyidct(
    const float* __restrict__ qf, const float* __restrict__ kf,
    float* __restrict__ out)
{
    __shared__ float sm[8*SMP];
    __shared__ float at[256];
    __shared__ float M[64];
    int bh = blockIdx.y; int b = bh >> 2, h = bh & 3;
    int tid = threadIdx.x;
    if (tid < 64) M[tid] = g_IDCTM[tid];
    at[tid]       = g_attn[bh*256 + tid];
    at[tid + 128] = g_attn[bh*256 + tid + 128];
    int pos0 = blockIdx.x * 8;
    int pp_l = tid >> 4;
    int ab_l = (tid & 15) * 4;
    #pragma unroll 4
    for (int d = 0; d < 16; d++) {
        size_t off = (((size_t)(b*64 + h*16 + d))*2304 + pos0)*64 + tid*4;
        float4 vq = *(const float4*)(qf + off);
        float4 vk = *(const float4*)(kf + off);
        float4 v = make_float4(vq.x*vk.x, vq.y*vk.y, vq.z*vk.z, vq.w*vk.w);
        *(float4*)(sm + pp_l*SMP + d*64 + ab_l) = v;
    }
    __syncthreads();

    int pp = tid >> 4, cd = tid & 15;
    const float* arow = at + cd*16;
    float X[64];
    #pragma unroll
    for (int i = 0; i < 64; i++) X[i] = 0.f;
    #pragma unroll
    for (int d = 0; d < 16; d++) {
        float av = arow[d];
        const float4* s4 = (const float4*)(sm + pp*SMP + d*64);
        #pragma unroll
        for (int q4 = 0; q4 < 16; q4++) {
            float4 v = s4[q4];
            X[q4*4+0] += av * v.x;
            X[q4*4+1] += av * v.y;
            X[q4*4+2] += av * v.z;
            X[q4*4+3] += av * v.w;
        }
    }
    float tmp[8][8];
    #pragma unroll
    for (int a = 0; a < 8; a++) {
        #pragma unroll
        for (int n = 0; n < 8; n++) {
            float s = 0.f;
            #pragma unroll
            for (int bq = 0; bq < 8; bq++) s += X[a*8+bq] * M[n*8+bq];
            tmp[a][n] = s;
        }
    }
    int pos = pos0 + pp;
    int ph = pos / WW, pw = pos % WW;
    int bc = b*64 + h*16 + cd;
    float* op = out + (size_t)bc*HW + ph*8*Ww + pw*8;
    #pragma unroll
    for (int m = 0; m < 8; m++) {
        float y[8];
        #pragma unroll
        for (int n = 0; n < 8; n++) {
            float s = 0.f;
            #pragma unroll
            for (int a = 0; a < 8; a++) s += M[m*8+a] * tmp[a][n];
            y[n] = s;
        }
        *(float4*)(op + m*Ww)     = make_float4(y[0], y[1], y[2], y[3]);
        *(float4*)(op + m*Ww + 4) = make_float4(y[4], y[5], y[6], y[7]);
    }
}

// ------------------- fully fused pool (v = dw3(nh) inline) ----------------
// out = dw3(prelu(dw3(q*o,w1a),a1),w1b) + dw3(prelu(dw3(v-lam*v*o,w2a),a2),w2b)
// v computed from nir_hidden[64+ch] via 38x38 smem halo.
#define N38 38
#define TT 36
#define UT 34
__global__ void __launch_bounds__(256) k_poolF(
    const float* __restrict__ q, const float* __restrict__ o,
    const float* __restrict__ nh, const float* __restrict__ wdwn,
    const float* __restrict__ w1a, const float* __restrict__ w2a,
    const float* __restrict__ a1p, const float* __restrict__ a2p,
    const float* __restrict__ w1b, const float* __restrict__ w2b,
    float* __restrict__ out)
{
    __shared__ float nn[N38*N38];
    __shared__ float st1[TT*TT], st2[TT*TT];
    __shared__ float su1[UT*UT], su2[UT*UT];
    int tid = threadIdx.x;
    int tx = blockIdx.x % 12, ty = blockIdx.x / 12;
    int x0 = tx*32, y0 = ty*32;
    int bc = blockIdx.y;
    int ch = bc & 63, b = bc >> 6;
    const float* qp = q + (size_t)bc*HW;
    const float* op = o + (size_t)bc*HW;
    const float* np = nh + ((size_t)b*128 + 64 + ch)*HW;
    float lam = g_lam;

    // stage nir_hidden halo (38x38 at origin y0-3, x0-3)
    for (int i = tid; i < N38*N38; i += 256) {
        int ly = i / N38, lx = i - ly*N38;
        int gy = y0 + ly - 3, gx = x0 + lx - 3;
        nn[i] = ((unsigned)gy < (unsigned)Hh && (unsigned)gx < (unsigned)Ww)
              ? np[gy*Ww + gx] : 0.f;
    }
    float wv[9], wa1[9], wa2[9];
    #pragma unroll
    for (int i = 0; i < 9; i++) {
        wv[i]  = __ldg(wdwn + (64+ch)*9 + i);
        wa1[i] = __ldg(w1a + ch*9 + i);
        wa2[i] = __ldg(w2a + ch*9 + i);
    }
    float a1 = __ldg(a1p), a2 = __ldg(a2p);
    __syncthreads();

    // t stage (36x36): v = dw3(nn); t1 = q*o; t2 = v - lam*v*o
    for (int i = tid; i < TT*TT; i += 256) {
        int ly = i / TT, lx = i - ly*TT;
        int gy = y0 + ly - 2, gx = x0 + lx - 2;
        float t1 = 0.f, t2 = 0.f;
        if ((unsigned)gy < (unsigned)Hh && (unsigned)gx < (unsigned)Ww) {
            float vv = 0.f;
            #pragma unroll
            for (int dy = 0; dy < 3; dy++) {
                const float* n3 = nn + (ly+dy)*N38 + lx;
                const float* w3 = wv + dy*3;
                #pragma unroll
                for (int dx = 0; dx < 3; dx++) vv += w3[dx] * n3[dx];
            }
            int gi = gy*Ww + gx;
            float qv = qp[gi], ov = op[gi];
            t1 = qv * ov;
            t2 = vv - lam * (vv * ov);
        }
        st1[i] = t1; st2[i] = t2;
    }
    __syncthreads();

    // u stage (34x34)
    for (int i = tid; i < UT*UT; i += 256) {
        int ly = i / UT, lx = i - ly*UT;
        int gy = y0 + ly - 1, gx = x0 + lx - 1;
        float u1 = 0.f, u2 = 0.f;
        if ((unsigned)gy < (unsigned)Hh && (unsigned)gx < (unsigned)Ww) {
            float s1 = 0.f, s2 = 0.f;
            #pragma unroll
            for (int dy = 0; dy < 3; dy++) {
                const float* r1 = st1 + (ly+dy)*TT + lx;
                const float* r2 = st2 + (ly+dy)*TT + lx;
                #pragma unroll
                for (int dx = 0; dx < 3; dx++) {
                    s1 += wa1[dy*3+dx] * r1[dx];
                    s2 += wa2[dy*3+dx] * r2[dx];
                }
            }
            u1 = (s1 >= 0.f) ? s1 : a1*s1;
            u2 = (s2 >= 0.f) ? s2 : a2*s2;
        }
        su1[i] = u1; su2[i] = u2;
    }
    float wb1[9], wb2[9];
    #pragma unroll
    for (int i = 0; i < 9; i++) { wb1[i] = __ldg(w1b + ch*9 + i); wb2[i] = __ldg(w2b + ch*9 + i); }
    __syncthreads();

    // output 32x32
    for (int i = tid; i < 1024; i += 256) {
        int oy = i >> 5, ox = i & 31;
        float s = 0.f;
        #pragma unroll
        for (int dy = 0; dy < 3; dy++) {
            const float* r1 = su1 + (oy+dy)*UT + ox;
            const float* r2 = su2 + (oy+dy)*UT + ox;
            #pragma unroll
            for (int dx = 0; dx < 3; dx++) {
                s += wb1[dy*3+dx] * r1[dx] + wb2[dy*3+dx] * r2[dx];
            }
        }
        out[(size_t)bc*HW + (y0+oy)*Ww + x0 + ox] = s;
    }
}

// ------------------- host launcher ----------------------------------------
extern "C" void kernel_launch(void* const* d_in, const int* in_sizes, int n_in,
                              void* d_out, int out_size)
{
    const float* x            = (const float*)d_in[0];
    const float* nir          = (const float*)d_in[1];
    const float* w_hidden     = (const float*)d_in[2];
    const float* w_hidden_nir = (const float*)d_in[3];
    const float* w_dw         = (const float*)d_in[4];
    const float* w_dw_nir     = (const float*)d_in[5];
    const float* temperature  = (const float*)d_in[6];
    const float* w_proj_mid   = (const float*)d_in[7];
    const float* w_proj_out   = (const float*)d_in[8];
    const float* w_p1a        = (const float*)d_in[9];
    const float* a_p1         = (const float*)d_in[10];
    const float* w_p1b        = (const float*)d_in[11];
    const float* w_p2a        = (const float*)d_in[12];
    const float* a_p2         = (const float*)d_in[13];
    const float* w_p2b        = (const float*)d_in[14];
    const float* lq1          = (const float*)d_in[15];
    const float* lk1          = (const float*)d_in[16];
    const float* lq2          = (const float*)d_in[17];
    const float* lk2          = (const float*)d_in[18];

    float *A, *Bf, *Cf, *E, *F, *G;
    cudaGetSymbolAddress((void**)&A,  g_bA);
    cudaGetSymbolAddress((void**)&Bf, g_bB);
    cudaGetSymbolAddress((void**)&Cf, g_bC);
    cudaGetSymbolAddress((void**)&E,  g_bE);
    cudaGetSymbolAddress((void**)&F,  g_bF);
    cudaGetSymbolAddress((void**)&G,  g_bG);

    cudaFuncSetAttribute(k_conv1x1, cudaFuncAttributeMaxDynamicSharedMemorySize, CONV_SMEM);

    // launch order: slot 5 (ncu -s 5 -c 1) lands on k_dct2
    k_init<<<1, 64>>>(lq1, lk1, lq2, lk2);                                          // 1
    k_conv1x1<<<dim3(HW/128, Bb, 1), 128, CONV_SMEM>>>(x, w_hidden, A, 64, 0);      // 2
    k_dw3v2<<<NTOT/2048, 256>>>(A, w_dw, Cf, 64, 0);                                // 3: q
    k_conv1x1<<<dim3(HW/128, Bb, 2), 128, CONV_SMEM>>>(nir, w_hidden_nir, Bf, 128, 0);  // 4

    // fused q-DCT + inline-dw3(k)-DCT: qf(E), kf(F), sumsq                  // 5 <- profiled
    k_dct2<<<NPATCH/128, 128>>>(Cf, Bf, w_dw_nir, E, F);

    // attention
    k_dot<<<dim3(36, 8), 256>>>(E, F);
    k_softmax<<<8, 256>>>(temperature);
    k_applyidct<<<dim3(HH*WW/8, 8), 128>>>(E, F, A);   // o_spatial -> A

    // out = W_pm @ o  -> E (qf dead after applyidct)
    k_conv1x1<<<dim3(HW/128, Bb, 1), 128, CONV_SMEM>>>(A, w_proj_mid, E, 64, 0);

    // fully fused pools (v inline) -> G
    k_poolF<<<dim3(144, 128), 256>>>(Cf, E, Bf, w_dw_nir,
                                     w_p1a, w_p2a, a_p1, a_p2,
                                     w_p1b, w_p2b, G);

    // final projection
    k_conv1x1<<<dim3(HW/128, Bb, 1), 128, CONV_SMEM>>>(G, w_proj_out, (float*)d_out, 64, 0);
}

// round 17
// speedup vs baseline: 1.0880x; 1.0880x over previous
#include <cuda_runtime.h>
#include <math.h>

#define Bb 2
#define Cc 64
#define Hh 384
#define Ww 384
#define HW (Hh*Ww)            // 147456
#define NTOT (Bb*Cc*HW)       // 18874368
#define HH 48
#define WW 48
#define LLEN HW               // 147456
#define NPATCH (Bb*Cc*HH*WW)  // 294912

typedef unsigned long long ull;

// ------------------- scratch (device globals) -----------------------------
__device__ float g_bA[NTOT];      // hidden -> o_spatial
__device__ float g_bB[2*NTOT];    // nir_hidden (128 ch/batch)
__device__ float g_bC[NTOT];      // q
__device__ float g_bD[NTOT];      // v (compact 64 ch/batch)
__device__ float g_bE[NTOT];      // qf -> conv_mid out
__device__ float g_bF[NTOT];      // kf
__device__ float g_bG[NTOT];      // pooled output

__device__ float g_DCTM[64];      // [a*8+m]
__device__ float g_IDCTM[64];     // [m*8+a]
__device__ float g_sqq[128];
__device__ float g_sqk[128];
__device__ float g_S[8*256];
__device__ float g_attn[8*256];
__device__ float g_lam;

// ------------------- packed f32x2 helpers (sm_100+) -----------------------
__device__ __forceinline__ ull pk2(float lo, float hi) {
    ull r; asm("mov.b64 %0, {%1,%2};" : "=l"(r) : "f"(lo), "f"(hi)); return r;
}
#define FMA2(d, a, b, c) asm("fma.rn.f32x2 %0, %1, %2, %3;" : "=l"(d) : "l"(a), "l"(b), "l"(c))

// ------------------- init ---------------------------------------------------
__global__ void k_init(const float* __restrict__ lq1, const float* __restrict__ lk1,
                       const float* __restrict__ lq2, const float* __restrict__ lk2)
{
    int t = threadIdx.x;  // 64 threads
    if (t < 64) {
        int a = t >> 3, m = t & 7;
        double cv = 2.0 * cos(3.14159265358979323846 * (double)((2*m+1)*a) / 16.0);
        g_DCTM[a*8+m] = (float)cv;
        g_IDCTM[m*8+a] = (float)(cv / (a == 0 ? 32.0 : 16.0));
    }
    if (t < 32) {
        float s1 = lq1[t]*lk1[t] + lq1[t+32]*lk1[t+32];
        float s2 = lq2[t]*lk2[t] + lq2[t+32]*lk2[t+32];
        #pragma unroll
        for (int off = 16; off; off >>= 1) {
            s1 += __shfl_xor_sync(0xffffffffu, s1, off);
            s2 += __shfl_xor_sync(0xffffffffu, s2, off);
        }
        if (t == 0) {
            float lam_init = 0.8f - 0.6f * (float)exp(-1.8);
            g_lam = expf(s1) - expf(s2) + lam_init;
        }
    }
    for (int i = t; i < 2048; i += 64) g_S[i] = 0.f;
    for (int i = t; i < 128;  i += 64) { g_sqq[i] = 0.f; g_sqk[i] = 0.f; }
}

// ------------------- conv1x1 (R15 variant — near FFMA2 floor) --------------
#define WKS 68
__global__ void __launch_bounds__(128, 4) k_conv1x1(
    const float* __restrict__ in, const float* __restrict__ w,
    float* __restrict__ out, int OCtot, int ocOff)
{
    extern __shared__ char smraw[];
    float* wsf = (float*)smraw;                      // [64 k][68 oc]  17.4KB
    float* xs  = (float*)(smraw + 64*WKS*4);         // [64 ic][128 px] 32KB
    int ocBase = blockIdx.z * 64 + ocOff;
    int b = blockIdx.y;
    int tid = threadIdx.x;

    #pragma unroll
    for (int r = 0; r < 32; r++) {
        int t = r*128 + tid;           // t = oc*64 + k
        int oc = t >> 6, k = t & 63;
        wsf[k*WKS + oc] = __ldg(w + ocBase*64 + t);
    }
    const float* inb = in + (size_t)b*64*HW + blockIdx.x*128;
    #pragma unroll
    for (int r = 0; r < 16; r++) {
        int idx = r*128 + tid;
        int ic  = idx >> 5;
        int c4  = (idx & 31) * 4;
        *(float4*)(xs + ic*128 + c4) = *(const float4*)(inb + (size_t)ic*HW + c4);
    }
    __syncthreads();

    int ocg = tid >> 4;
    int pxg = tid & 15;
    int oc0 = ocg * 8;
    int px0 = pxg * 4;

    ull acc[8][4];
    #pragma unroll
    for (int j = 0; j < 8; j++)
        #pragma unroll
        for (int t = 0; t < 4; t++) acc[j][t] = 0ULL;

    #pragma unroll 4
    for (int k = 0; k < 64; k++) {
        const float* wr = wsf + k*WKS + oc0;
        float4 w0 = *(const float4*)(wr);
        float4 w1 = *(const float4*)(wr + 4);
        const float* xr = xs + k*128 + px0;
        ulonglong2 p0 = *(const ulonglong2*)(xr);
        ulonglong2 p1 = *(const ulonglong2*)(xr + 64);
        float wf[8] = {w0.x, w0.y, w0.z, w0.w, w1.x, w1.y, w1.z, w1.w};
        #pragma unroll
        for (int j = 0; j < 8; j++) {
            ull wv = pk2(wf[j], wf[j]);
            FMA2(acc[j][0], wv, p0.x, acc[j][0]);
            FMA2(acc[j][1], wv, p0.y, acc[j][1]);
            FMA2(acc[j][2], wv, p1.x, acc[j][2]);
            FMA2(acc[j][3], wv, p1.y, acc[j][3]);
        }
    }

    float* outb = out + ((size_t)b*OCtot + ocBase + oc0)*HW + blockIdx.x*128 + px0;
    #pragma unroll
    for (int j = 0; j < 8; j++) {
        ulonglong2 v0; v0.x = acc[j][0]; v0.y = acc[j][1];
        ulonglong2 v1; v1.x = acc[j][2]; v1.y = acc[j][3];
        *(ulonglong2*)(outb + (size_t)j*HW)      = v0;
        *(ulonglong2*)(outb + (size_t)j*HW + 64) = v1;
    }
}
#define CONV_SMEM (64*WKS*4 + 32768)

// ------------------- row loader: 6 values around aligned 4-px group -------
__device__ __forceinline__ void load6(const float* __restrict__ row, int x, float v[6])
{
    float4 c = *(const float4*)(row + x);
    v[1] = c.x; v[2] = c.y; v[3] = c.z; v[4] = c.w;
    v[0] = (x > 0)      ? row[x-1] : 0.f;
    v[5] = (x+4 < Ww)   ? row[x+4] : 0.f;
}

// ------------------- depthwise 3x3, 8 px/thread, channel-slice ------------
__global__ void __launch_bounds__(256) k_dw3v2(
    const float* __restrict__ in, const float* __restrict__ w9,
    float* __restrict__ out, int inChPerB, int chOff)
{
    int g = blockIdx.x*256 + threadIdx.x;
    int x  = (g % 96) * 4;
    int y  = ((g / 96) % 192) * 2;
    int bc = g / 18432;                 // 96*192
    int b = bc >> 6, ch = bc & 63;
    int wch = chOff + ch;
    const float* ip = in + ((size_t)b*inChPerB + wch)*HW;
    float w[9];
    #pragma unroll
    for (int i = 0; i < 9; i++) w[i] = __ldg(w9 + wch*9 + i);

    float vr[4][6];
    #pragma unroll
    for (int r = 0; r < 4; r++) {
        int yy = y - 1 + r;
        if ((unsigned)yy < (unsigned)Hh) load6(ip + yy*Ww, x, vr[r]);
        else { vr[r][0]=0.f; vr[r][1]=0.f; vr[r][2]=0.f; vr[r][3]=0.f; vr[r][4]=0.f; vr[r][5]=0.f; }
    }
    float a0[4] = {0,0,0,0}, a1[4] = {0,0,0,0};
    #pragma unroll
    for (int dy = 0; dy < 3; dy++) {
        const float* wr = w + dy*3;
        #pragma unroll
        for (int j = 0; j < 4; j++) {
            a0[j] += wr[0]*vr[dy][j]   + wr[1]*vr[dy][j+1]   + wr[2]*vr[dy][j+2];
            a1[j] += wr[0]*vr[dy+1][j] + wr[1]*vr[dy+1][j+1] + wr[2]*vr[dy+1][j+2];
        }
    }
    float* op = out + (size_t)bc*HW + y*Ww + x;
    *(float4*)(op)      = make_float4(a0[0], a0[1], a0[2], a0[3]);
    *(float4*)(op + Ww) = make_float4(a1[0], a1[1], a1[2], a1[3]);
}

// ------------------- load 10 halo floats (cols x0-1..x0+8) of one row -----
__device__ __forceinline__ void loadrow10(const float* __restrict__ ip,
                                          int y, int x0, float f[10])
{
    if ((unsigned)y >= (unsigned)Hh) {
        #pragma unroll
        for (int i = 0; i < 10; i++) f[i] = 0.f;
        return;
    }
    const float* row = ip + y*Ww;
    float4 b0 = *(const float4*)(row + x0);
    float4 b1 = *(const float4*)(row + x0 + 4);
    f[1]=b0.x; f[2]=b0.y; f[3]=b0.z; f[4]=b0.w;
    f[5]=b1.x; f[6]=b1.y; f[7]=b1.z; f[8]=b1.w;
    f[0] = (x0 > 0)      ? row[x0-1] : 0.f;
    f[9] = (x0+8 < Ww)   ? row[x0+8] : 0.f;
}

// ------------------- fused: q-DCT + inline-dw3(k)-DCT + sumsq -------------
__global__ void __launch_bounds__(128) k_dct2(
    const float* __restrict__ q, const float* __restrict__ nh,
    const float* __restrict__ wdwn,
    float* __restrict__ qf, float* __restrict__ kf)
{
    __shared__ float M[64];
    __shared__ float redq[4], redk[4];
    int tid = threadIdx.x;
    if (tid < 64) M[tid] = g_DCTM[tid];
    __syncthreads();
    int p = blockIdx.x*128 + tid;
    int pw = p % WW;
    int t2 = p / WW;
    int ph = t2 % HH;
    int bc = t2 / HH;
    int b = bc >> 6, ch = bc & 63;

    // ---- q DCT ----
    const float* ipq = q + (size_t)bc*HW + ph*8*Ww + pw*8;
    float tmp[8][8];
    #pragma unroll
    for (int m = 0; m < 8; m++) {
        float4 v0 = *(const float4*)(ipq + m*Ww);
        float4 v1 = *(const float4*)(ipq + m*Ww + 4);
        float r[8] = {v0.x, v0.y, v0.z, v0.w, v1.x, v1.y, v1.z, v1.w};
        #pragma unroll
        for (int bb = 0; bb < 8; bb++) {
            float s = 0.f;
            #pragma unroll
            for (int n = 0; n < 8; n++) s += r[n] * M[bb*8+n];
            tmp[m][bb] = s;
        }
    }
    float* qp = qf + (size_t)p*64;
    float ssq = 0.f;
    #pragma unroll
    for (int a = 0; a < 8; a++) {
        float y[8];
        #pragma unroll
        for (int bb = 0; bb < 8; bb++) {
            float s = 0.f;
            #pragma unroll
            for (int m = 0; m < 8; m++) s += M[a*8+m] * tmp[m][bb];
            y[bb] = s;
            ssq += s*s;
        }
        *(float4*)(qp + a*8)     = make_float4(y[0], y[1], y[2], y[3]);
        *(float4*)(qp + a*8 + 4) = make_float4(y[4], y[5], y[6], y[7]);
    }

    // ---- k = dw3(nir_hidden[ch]) computed inline, then DCT ----
    const float* ipk = nh + ((size_t)b*128 + ch)*HW;
    float wk[9];
    #pragma unroll
    for (int i = 0; i < 9; i++) wk[i] = __ldg(wdwn + ch*9 + i);
    int y0 = ph*8, x0 = pw*8;

    float rA[10], rB[10], rC[10];
    loadrow10(ipk, y0-1, x0, rA);
    loadrow10(ipk, y0,   x0, rB);
    #pragma unroll
    for (int m = 0; m < 8; m++) {
        loadrow10(ipk, y0+m+1, x0, rC);
        float r[8];
        #pragma unroll
        for (int j = 0; j < 8; j++) {
            r[j] = wk[0]*rA[j] + wk[1]*rA[j+1] + wk[2]*rA[j+2]
                 + wk[3]*rB[j] + wk[4]*rB[j+1] + wk[5]*rB[j+2]
                 + wk[6]*rC[j] + wk[7]*rC[j+1] + wk[8]*rC[j+2];
        }
        #pragma unroll
        for (int bb = 0; bb < 8; bb++) {
            float s = 0.f;
            #pragma unroll
            for (int n = 0; n < 8; n++) s += r[n] * M[bb*8+n];
            tmp[m][bb] = s;
        }
        #pragma unroll
        for (int i = 0; i < 10; i++) { rA[i] = rB[i]; rB[i] = rC[i]; }
    }
    float* kp = kf + (size_t)p*64;
    float ssk = 0.f;
    #pragma unroll
    for (int a = 0; a < 8; a++) {
        float y[8];
        #pragma unroll
        for (int bb = 0; bb < 8; bb++) {
            float s = 0.f;
            #pragma unroll
            for (int m = 0; m < 8; m++) s += M[a*8+m] * tmp[m][bb];
            y[bb] = s;
            ssk += s*s;
        }
        *(float4*)(kp + a*8)     = make_float4(y[0], y[1], y[2], y[3]);
        *(float4*)(kp + a*8 + 4) = make_float4(y[4], y[5], y[6], y[7]);
    }

    #pragma unroll
    for (int off = 16; off; off >>= 1) {
        ssq += __shfl_xor_sync(0xffffffffu, ssq, off);
        ssk += __shfl_xor_sync(0xffffffffu, ssk, off);
    }
    int lane = tid & 31, wd = tid >> 5;
    if (lane == 0) { redq[wd] = ssq; redk[wd] = ssk; }
    __syncthreads();
    if (tid == 0) {
        atomicAdd(&g_sqq[bc], redq[0]+redq[1]+redq[2]+redq[3]);
        atomicAdd(&g_sqk[bc], redk[0]+redk[1]+redk[2]+redk[3]);
    }
}

// ------------------- Gram matrices S[bh][c][d] = <qf_c, kf_d> -------------
__global__ void k_dot(const float* __restrict__ qf, const float* __restrict__ kf)
{
    int bh = blockIdx.y; int b = bh >> 2, h = bh & 3;
    const float* qb = qf + ((size_t)b*64 + h*16)*LLEN;
    const float* kb = kf + ((size_t)b*64 + h*16)*LLEN;
    int tid = threadIdx.x;
    int c = tid >> 4, d = tid & 15;
    __shared__ float qs[16][65], ks[16][65];
    float acc = 0.f;
    int l0 = blockIdx.x * 4096;
    for (int lt = 0; lt < 4096; lt += 64) {
        int base = l0 + lt;
        for (int t = tid; t < 1024; t += 256) {
            int r = t >> 6, i = t & 63;
            qs[r][i] = qb[(size_t)r*LLEN + base + i];
            ks[r][i] = kb[(size_t)r*LLEN + base + i];
        }
        __syncthreads();
        #pragma unroll
        for (int i = 0; i < 64; i++) acc += qs[c][i] * ks[d][i];
        __syncthreads();
    }
    atomicAdd(&g_S[bh*256 + tid], acc);
}

// ------------------- finalize logits + softmax over d ---------------------
__global__ void k_softmax(const float* __restrict__ temp)
{
    int bh = blockIdx.x; int b = bh >> 2, h = bh & 3;
    int tid = threadIdx.x; int c = tid >> 4, d = tid & 15;
    float nq = fmaxf(sqrtf(g_sqq[b*64 + h*16 + c]), 1e-12f);
    float nk = fmaxf(sqrtf(g_sqk[b*64 + h*16 + d]), 1e-12f);
    float logit = g_S[bh*256 + tid] / (nq*nk) * temp[h];
    float mx = logit;
    #pragma unroll
    for (int off = 8; off; off >>= 1)
        mx = fmaxf(mx, __shfl_xor_sync(0xffffffffu, mx, off, 16));
    float e = expf(logit - mx);
    float s = e;
    #pragma unroll
    for (int off = 8; off; off >>= 1)
        s += __shfl_xor_sync(0xffffffffu, s, off, 16);
    g_attn[bh*256 + tid] = e / s;
}

// ------------------- fused attn-apply + IDCT (out1 = qf*kf on the fly) ----
#define SMP 1028   // padded stride per patch (floats)
__global__ void __launch_bounds__(128) k_applyidct(
    const float* __restrict__ qf, const float* __restrict__ kf,
    float* __restrict__ out)
{
    __shared__ float sm[8*SMP];
    __shared__ float at[256];
    __shared__ float M[64];
    int bh = blockIdx.y; int b = bh >> 2, h = bh & 3;
    int tid = threadIdx.x;
    if (tid < 64) M[tid] = g_IDCTM[tid];
    at[tid]       = g_attn[bh*256 + tid];
    at[tid + 128] = g_attn[bh*256 + tid + 128];
    int pos0 = blockIdx.x * 8;
    int pp_l = tid >> 4;
    int ab_l = (tid & 15) * 4;
    #pragma unroll 4
    for (int d = 0; d < 16; d++) {
        size_t off = (((size_t)(b*64 + h*16 + d))*2304 + pos0)*64 + tid*4;
        float4 vq = *(const float4*)(qf + off);
        float4 vk = *(const float4*)(kf + off);
        float4 v = make_float4(vq.x*vk.x, vq.y*vk.y, vq.z*vk.z, vq.w*vk.w);
        *(float4*)(sm + pp_l*SMP + d*64 + ab_l) = v;
    }
    __syncthreads();

    int pp = tid >> 4, cd = tid & 15;
    const float* arow = at + cd*16;
    float X[64];
    #pragma unroll
    for (int i = 0; i < 64; i++) X[i] = 0.f;
    #pragma unroll
    for (int d = 0; d < 16; d++) {
        float av = arow[d];
        const float4* s4 = (const float4*)(sm + pp*SMP + d*64);
        #pragma unroll
        for (int q4 = 0; q4 < 16; q4++) {
            float4 v = s4[q4];
            X[q4*4+0] += av * v.x;
            X[q4*4+1] += av * v.y;
            X[q4*4+2] += av * v.z;
            X[q4*4+3] += av * v.w;
        }
    }
    float tmp[8][8];
    #pragma unroll
    for (int a = 0; a < 8; a++) {
        #pragma unroll
        for (int n = 0; n < 8; n++) {
            float s = 0.f;
            #pragma unroll
            for (int bq = 0; bq < 8; bq++) s += X[a*8+bq] * M[n*8+bq];
            tmp[a][n] = s;
        }
    }
    int pos = pos0 + pp;
    int ph = pos / WW, pw = pos % WW;
    int bc = b*64 + h*16 + cd;
    float* op = out + (size_t)bc*HW + ph*8*Ww + pw*8;
    #pragma unroll
    for (int m = 0; m < 8; m++) {
        float y[8];
        #pragma unroll
        for (int n = 0; n < 8; n++) {
            float s = 0.f;
            #pragma unroll
            for (int a = 0; a < 8; a++) s += M[m*8+a] * tmp[a][n];
            y[n] = s;
        }
        *(float4*)(op + m*Ww)     = make_float4(y[0], y[1], y[2], y[3]);
        *(float4*)(op + m*Ww + 4) = make_float4(y[4], y[5], y[6], y[7]);
    }
}

// ------------------- fully fused pool (R15 version — materialized v) ------
#define TT 36
#define UT 34
__global__ void __launch_bounds__(256) k_poolF(
    const float* __restrict__ q, const float* __restrict__ o,
    const float* __restrict__ v,
    const float* __restrict__ w1a, const float* __restrict__ w2a,
    const float* __restrict__ a1p, const float* __restrict__ a2p,
    const float* __restrict__ w1b, const float* __restrict__ w2b,
    float* __restrict__ out)
{
    __shared__ float st1[TT*TT], st2[TT*TT];
    __shared__ float su1[UT*UT], su2[UT*UT];
    int tid = threadIdx.x;
    int tx = blockIdx.x % 12, ty = blockIdx.x / 12;
    int x0 = tx*32, y0 = ty*32;
    int bc = blockIdx.y;
    int ch = bc & 63;
    const float* qp = q + (size_t)bc*HW;
    const float* op = o + (size_t)bc*HW;
    const float* vp = v + (size_t)bc*HW;
    float lam = g_lam;

    for (int i = tid; i < TT*TT; i += 256) {
        int ly = i / TT, lx = i - ly*TT;
        int gy = y0 + ly - 2, gx = x0 + lx - 2;
        float t1 = 0.f, t2 = 0.f;
        if ((unsigned)gy < (unsigned)Hh && (unsigned)gx < (unsigned)Ww) {
            int gi = gy*Ww + gx;
            float qv = qp[gi], ov = op[gi], vv = vp[gi];
            t1 = qv * ov;
            t2 = vv - lam * (vv * ov);
        }
        st1[i] = t1; st2[i] = t2;
    }
    float wa1[9], wa2[9];
    #pragma unroll
    for (int i = 0; i < 9; i++) { wa1[i] = __ldg(w1a + ch*9 + i); wa2[i] = __ldg(w2a + ch*9 + i); }
    float a1 = __ldg(a1p), a2 = __ldg(a2p);
    __syncthreads();

    for (int i = tid; i < UT*UT; i += 256) {
        int ly = i / UT, lx = i - ly*UT;
        int gy = y0 + ly - 1, gx = x0 + lx - 1;
        float u1 = 0.f, u2 = 0.f;
        if ((unsigned)gy < (unsigned)Hh && (unsigned)gx < (unsigned)Ww) {
            float s1 = 0.f, s2 = 0.f;
            #pragma unroll
            for (int dy = 0; dy < 3; dy++) {
                const float* r1 = st1 + (ly+dy)*TT + lx;
                const float* r2 = st2 + (ly+dy)*TT + lx;
                #pragma unroll
                for (int dx = 0; dx < 3; dx++) {
                    s1 += wa1[dy*3+dx] * r1[dx];
                    s2 += wa2[dy*3+dx] * r2[dx];
                }
            }
            u1 = (s1 >= 0.f) ? s1 : a1*s1;
            u2 = (s2 >= 0.f) ? s2 : a2*s2;
        }
        su1[i] = u1; su2[i] = u2;
    }
    float wb1[9], wb2[9];
    #pragma unroll
    for (int i = 0; i < 9; i++) { wb1[i] = __ldg(w1b + ch*9 + i); wb2[i] = __ldg(w2b + ch*9 + i); }
    __syncthreads();

    for (int i = tid; i < 1024; i += 256) {
        int oy = i >> 5, ox = i & 31;
        float s = 0.f;
        #pragma unroll
        for (int dy = 0; dy < 3; dy++) {
            const float* r1 = su1 + (oy+dy)*UT + ox;
            const float* r2 = su2 + (oy+dy)*UT + ox;
            #pragma unroll
            for (int dx = 0; dx < 3; dx++) {
                s += wb1[dy*3+dx] * r1[dx] + wb2[dy*3+dx] * r2[dx];
            }
        }
        out[(size_t)bc*HW + (y0+oy)*Ww + x0 + ox] = s;
    }
}

// ------------------- host launcher ----------------------------------------
extern "C" void kernel_launch(void* const* d_in, const int* in_sizes, int n_in,
                              void* d_out, int out_size)
{
    const float* x            = (const float*)d_in[0];
    const float* nir          = (const float*)d_in[1];
    const float* w_hidden     = (const float*)d_in[2];
    const float* w_hidden_nir = (const float*)d_in[3];
    const float* w_dw         = (const float*)d_in[4];
    const float* w_dw_nir     = (const float*)d_in[5];
    const float* temperature  = (const float*)d_in[6];
    const float* w_proj_mid   = (const float*)d_in[7];
    const float* w_proj_out   = (const float*)d_in[8];
    const float* w_p1a        = (const float*)d_in[9];
    const float* a_p1         = (const float*)d_in[10];
    const float* w_p1b        = (const float*)d_in[11];
    const float* w_p2a        = (const float*)d_in[12];
    const float* a_p2         = (const float*)d_in[13];
    const float* w_p2b        = (const float*)d_in[14];
    const float* lq1          = (const float*)d_in[15];
    const float* lk1          = (const float*)d_in[16];
    const float* lq2          = (const float*)d_in[17];
    const float* lk2          = (const float*)d_in[18];

    float *A, *Bf, *Cf, *D, *E, *F, *G;
    cudaGetSymbolAddress((void**)&A,  g_bA);
    cudaGetSymbolAddress((void**)&Bf, g_bB);
    cudaGetSymbolAddress((void**)&Cf, g_bC);
    cudaGetSymbolAddress((void**)&D,  g_bD);
    cudaGetSymbolAddress((void**)&E,  g_bE);
    cudaGetSymbolAddress((void**)&F,  g_bF);
    cudaGetSymbolAddress((void**)&G,  g_bG);

    cudaFuncSetAttribute(k_conv1x1, cudaFuncAttributeMaxDynamicSharedMemorySize, CONV_SMEM);

    // launch order: slot 5 (ncu -s 5 -c 1) lands on k_dct2
    k_init<<<1, 64>>>(lq1, lk1, lq2, lk2);                                          // 1
    k_conv1x1<<<dim3(HW/128, Bb, 1), 128, CONV_SMEM>>>(x, w_hidden, A, 64, 0);      // 2
    k_dw3v2<<<NTOT/2048, 256>>>(A, w_dw, Cf, 64, 0);                                // 3: q
    k_conv1x1<<<dim3(HW/128, Bb, 2), 128, CONV_SMEM>>>(nir, w_hidden_nir, Bf, 128, 0);  // 4 (merged)

    // fused q-DCT + inline-dw3(k)-DCT: qf(E), kf(F), sumsq                  // 5 <- profiled
    k_dct2<<<NPATCH/128, 128>>>(Cf, Bf, w_dw_nir, E, F);

    // v = dw3(nir_hidden[64:]) (needed only by poolF)
    k_dw3v2<<<NTOT/2048, 256>>>(Bf, w_dw_nir, D, 128, 64);

    // attention
    k_dot<<<dim3(36, 8), 256>>>(E, F);
    k_softmax<<<8, 256>>>(temperature);
    k_applyidct<<<dim3(HH*WW/8, 8), 128>>>(E, F, A);   // o_spatial -> A

    // out = W_pm @ o  -> E (qf dead after applyidct)
    k_conv1x1<<<dim3(HW/128, Bb, 1), 128, CONV_SMEM>>>(A, w_proj_mid, E, 64, 0);

    // fully fused pools -> G
    k_poolF<<<dim3(144, 128), 256>>>(Cf, E, D, w_p1a, w_p2a, a_p1, a_p2,
                                     w_p1b, w_p2b, G);

    // final projection
    k_conv1x1<<<dim3(HW/128, Bb, 1), 128, CONV_SMEM>>>(G, w_proj_out, (float*)d_out, 64, 0);
}